// round 2
// baseline (speedup 1.0000x reference)
#include <cuda_runtime.h>
#include <math.h>

#define LL_ (384*384)
#define LDIM 384

// ---------------- scratch (device globals; no allocation allowed) ----------
// float offsets into g_scratch
#define OFF_Q    0
#define OFF_K    98304
#define OFF_V    196608
#define OFF_A0   294912            // 16 * 147456 = 2359296
#define OFF_A1   2654208           // 8 * 147456 = 1179648
#define OFF_A2   3833856           // 8 * 147456
#define OFF_CAT  5013504           // 384*1280 = 491520
#define OFF_H1   5505024           // 384*512 = 196608
#define OFF_WT   5701632           // 136*9*128 = 156672
#define OFF_PART 5858304           // 96*128*2 = 24576
#define OFF_ST0  5882880           // 16 float2 = 32 floats
#define OFF_ST1  5882912           // 9 float2 = 18 -> pad to 20
#define OFF_STZ  5882932           // 136 float2 = 272 floats
#define SC_TOTAL 5883264

__device__ float g_scratch[SC_TOTAL];

// ---------------- K1: q,k,v = x @ W ----------------------------------------
__global__ void qkv_kernel(const float* __restrict__ x,
                           const float* __restrict__ Wq,
                           const float* __restrict__ Wk,
                           const float* __restrict__ Wv) {
    __shared__ float sx[256];
    int l = blockIdx.x, t = threadIdx.x;
    sx[t] = x[l * 256 + t];
    __syncthreads();
    float aq = 0.f, ak = 0.f, av = 0.f;
    for (int i = 0; i < 256; i++) {
        float xv = sx[i];
        aq += xv * Wq[i * 256 + t];
        ak += xv * Wk[i * 256 + t];
        av += xv * Wv[i * 256 + t];
    }
    g_scratch[OFF_Q + l * 256 + t] = aq;
    g_scratch[OFF_K + l * 256 + t] = ak;
    g_scratch[OFF_V + l * 256 + t] = av;
}

// ---------------- K2: a0[16,L,L]: pair scores + node scores ----------------
__global__ void score_kernel(const float* __restrict__ z,
                             const float* __restrict__ Wp2a) {
    __shared__ float s_z[16][129];
    __shared__ float s_q[256];
    __shared__ float s_k[16][257];
    __shared__ float s_wp[1024];
    int i = blockIdx.y, j0 = blockIdx.x * 16, t = threadIdx.x;  // 128 threads
    const float* q = g_scratch + OFF_Q;
    const float* k = g_scratch + OFF_K;
    for (int e = t; e < 1024; e += 128) s_wp[e] = Wp2a[e];
    for (int e = t; e < 256; e += 128) s_q[e] = q[i * 256 + e];
    for (int e = t; e < 16 * 128; e += 128) {
        int jl = e >> 7, p = e & 127;
        s_z[jl][p] = z[((size_t)i * LDIM + j0 + jl) * 128 + p];
    }
    for (int e = t; e < 16 * 256; e += 128) {
        int jl = e >> 8, d = e & 255;
        s_k[jl][d] = k[(j0 + jl) * 256 + d];
    }
    __syncthreads();
    int jl = t >> 3, h = t & 7;
    float ap = 0.f;
    for (int p = 0; p < 128; p++) ap += s_z[jl][p] * s_wp[p * 8 + h];
    float an = 0.f;
    for (int d = 0; d < 32; d++) an += s_q[h * 32 + d] * s_k[jl][h * 32 + d];
    an *= 0.17677669529663687f;  // 1/sqrt(32)
    int j = j0 + jl;
    g_scratch[OFF_A0 + (size_t)h * LL_ + i * LDIM + j] = ap;
    g_scratch[OFF_A0 + (size_t)(8 + h) * LL_ + i * LDIM + j] = an;
}

// ---------------- instance-norm stats, channel-first buffer ----------------
__global__ void stats_cf_kernel(const float* __restrict__ buf, float2* __restrict__ out) {
    int c = blockIdx.x, t = threadIdx.x;  // 256 threads
    const float* p = buf + (size_t)c * LL_;
    float s = 0.f, s2 = 0.f;
    for (int e = t; e < LL_; e += 256) { float v = p[e]; s += v; s2 += v * v; }
    __shared__ float rs[256], rs2[256];
    rs[t] = s; rs2[t] = s2; __syncthreads();
    for (int w = 128; w > 0; w >>= 1) {
        if (t < w) { rs[t] += rs[t + w]; rs2[t] += rs2[t + w]; }
        __syncthreads();
    }
    if (t == 0) {
        float m = rs[0] / (float)LL_;
        float var = rs2[0] / (float)LL_ - m * m;
        float sc = rsqrtf(var + 1e-5f);
        out[c] = make_float2(sc, -m * sc);
    }
}

// ---------------- generic fused norm+conv3x3+leaky, channel-first, Cout=8 --
__global__ void conv_cf_kernel(const float* __restrict__ in1, int C1,
                               const float* __restrict__ in2, int C2,
                               const float* __restrict__ w,
                               const float* __restrict__ b,
                               const float2* __restrict__ stats,
                               float* __restrict__ out) {
    __shared__ float s_in[16 * 3 * 66];
    __shared__ float s_w[1152];
    __shared__ float2 s_st[16];
    int Cin = C1 + C2;
    int i = blockIdx.y, j0 = blockIdx.x * 64, t = threadIdx.x;  // 256 threads
    if (t < Cin) s_st[t] = stats[t];
    __syncthreads();
    for (int e = t; e < Cin * 3 * 66; e += 256) {
        int col = e % 66;
        int r = (e / 66) % 3;
        int c = e / 198;
        int gi = i - 1 + r, gj = j0 - 1 + col;
        float v = 0.f;
        if (gi >= 0 && gi < LDIM && gj >= 0 && gj < LDIM) {
            float raw = (c < C1) ? in1[(size_t)c * LL_ + gi * LDIM + gj]
                                 : in2[(size_t)(c - C1) * LL_ + gi * LDIM + gj];
            float2 st = s_st[c];
            v = raw * st.x + st.y;
        }
        s_in[(c * 3 + r) * 66 + col] = v;
    }
    for (int e = t; e < 8 * Cin * 9; e += 256) s_w[e] = w[e];
    __syncthreads();
    int px = t & 63;
    int cg = t >> 6;  // co in {cg, cg+4}
    float a0 = 0.f, a1 = 0.f;
    for (int c = 0; c < Cin; c++)
        for (int r = 0; r < 3; r++)
            #pragma unroll
            for (int dc = 0; dc < 3; dc++) {
                float iv = s_in[(c * 3 + r) * 66 + px + dc];
                int wi = c * 9 + r * 3 + dc;
                a0 += iv * s_w[cg * Cin * 9 + wi];
                a1 += iv * s_w[(cg + 4) * Cin * 9 + wi];
            }
    int j = j0 + px;
    float v0 = a0 + b[cg];
    float v1 = a1 + b[cg + 4];
    out[(size_t)cg * LL_ + i * LDIM + j] = v0 >= 0.f ? v0 : 0.01f * v0;
    out[(size_t)(cg + 4) * LL_ + i * LDIM + j] = v1 >= 0.f ? v1 : 0.01f * v1;
}

// ---------------- K5: nfp[l,h,p] = sum_m a2[h,l,m] z[l,m,p] ----------------
__global__ void nfp_kernel(const float* __restrict__ z) {
    int l = blockIdx.x, t = threadIdx.x;  // 128 threads
    __shared__ float s_a[8 * 384];
    const float* a2 = g_scratch + OFF_A2;
    for (int e = t; e < 8 * 384; e += 128) {
        int h = e / 384, m = e % 384;
        s_a[e] = a2[(size_t)h * LL_ + l * 384 + m];
    }
    __syncthreads();
    float acc[8] = {0.f, 0.f, 0.f, 0.f, 0.f, 0.f, 0.f, 0.f};
    const float* zl = z + (size_t)l * 384 * 128;
    for (int m = 0; m < 384; m++) {
        float zv = zl[m * 128 + t];
        #pragma unroll
        for (int h = 0; h < 8; h++) acc[h] += s_a[h * 384 + m] * zv;
    }
    #pragma unroll
    for (int h = 0; h < 8; h++)
        g_scratch[OFF_CAT + (size_t)l * 1280 + h * 128 + t] = acc[h];
}

// ---------------- K6: nfn[l,h,d] = sum_m a2[h,l,m] v[m,h,d] ----------------
__global__ void nfn_kernel() {
    int l = blockIdx.x, t = threadIdx.x;  // 256 threads
    __shared__ float s_a[8 * 384];
    const float* a2 = g_scratch + OFF_A2;
    const float* v = g_scratch + OFF_V;
    for (int e = t; e < 8 * 384; e += 256) {
        int h = e / 384, m = e % 384;
        s_a[e] = a2[(size_t)h * LL_ + l * 384 + m];
    }
    __syncthreads();
    int h = t >> 5;
    float acc = 0.f;
    for (int m = 0; m < 384; m++) acc += s_a[h * 384 + m] * v[m * 256 + t];
    g_scratch[OFF_CAT + (size_t)l * 1280 + 1024 + t] = acc;
}

// ---------------- K7: h1 = LN(cat) @ W1 + b1 -------------------------------
__global__ void mlp1_kernel(const float* __restrict__ ln1w, const float* __restrict__ ln1b,
                            const float* __restrict__ w1, const float* __restrict__ b1) {
    int l = blockIdx.x, t = threadIdx.x;  // 256 threads
    __shared__ float u[1280];
    __shared__ float red[256];
    const float* row = g_scratch + OFF_CAT + (size_t)l * 1280;
    float s = 0.f;
    for (int e = t; e < 1280; e += 256) s += row[e];
    red[t] = s; __syncthreads();
    for (int w = 128; w > 0; w >>= 1) { if (t < w) red[t] += red[t + w]; __syncthreads(); }
    float mean = red[0] / 1280.f;
    __syncthreads();
    float s2 = 0.f;
    for (int e = t; e < 1280; e += 256) { float d = row[e] - mean; s2 += d * d; }
    red[t] = s2; __syncthreads();
    for (int w = 128; w > 0; w >>= 1) { if (t < w) red[t] += red[t + w]; __syncthreads(); }
    float inv = rsqrtf(red[0] / 1280.f + 1e-5f);
    for (int e = t; e < 1280; e += 256)
        u[e] = (row[e] - mean) * inv * ln1w[e] + ln1b[e];
    __syncthreads();
    for (int o = t; o < 512; o += 256) {
        float acc = b1[o];
        for (int e = 0; e < 1280; e++) acc += u[e] * w1[e * 512 + o];
        g_scratch[OFF_H1 + (size_t)l * 512 + o] = acc;
    }
}

// ---------------- K8: h2, residual, final LN -> x_new ----------------------
__global__ void mlp2_kernel(const float* __restrict__ ln2w, const float* __restrict__ ln2b,
                            const float* __restrict__ w2, const float* __restrict__ b2,
                            const float* __restrict__ x,
                            const float* __restrict__ lnfw, const float* __restrict__ lnfb,
                            float* __restrict__ xnew) {
    int l = blockIdx.x, t = threadIdx.x;  // 256 threads
    __shared__ float u[512];
    __shared__ float red[256];
    const float* row = g_scratch + OFF_H1 + (size_t)l * 512;
    float v0 = row[t], v1 = row[t + 256];
    red[t] = v0 + v1; __syncthreads();
    for (int w = 128; w > 0; w >>= 1) { if (t < w) red[t] += red[t + w]; __syncthreads(); }
    float mean = red[0] / 512.f;
    __syncthreads();
    float d0 = v0 - mean, d1 = v1 - mean;
    red[t] = d0 * d0 + d1 * d1; __syncthreads();
    for (int w = 128; w > 0; w >>= 1) { if (t < w) red[t] += red[t + w]; __syncthreads(); }
    float inv = rsqrtf(red[0] / 512.f + 1e-5f);
    __syncthreads();
    float n0 = d0 * inv * ln2w[t] + ln2b[t];
    float n1 = d1 * inv * ln2w[t + 256] + ln2b[t + 256];
    u[t] = n0 >= 0.f ? n0 : 0.01f * n0;
    u[t + 256] = n1 >= 0.f ? n1 : 0.01f * n1;
    __syncthreads();
    float acc = b2[t];
    for (int e = 0; e < 512; e++) acc += u[e] * w2[e * 256 + t];
    float rv = acc + x[l * 256 + t];
    red[t] = rv; __syncthreads();
    for (int w = 128; w > 0; w >>= 1) { if (t < w) red[t] += red[t + w]; __syncthreads(); }
    float m2 = red[0] / 256.f;
    __syncthreads();
    float dd = rv - m2;
    red[t] = dd * dd; __syncthreads();
    for (int w = 128; w > 0; w >>= 1) { if (t < w) red[t] += red[t + w]; __syncthreads(); }
    float inv2 = rsqrtf(red[0] / 256.f + 1e-5f);
    xnew[l * 256 + t] = dd * inv2 * lnfw[t] + lnfb[t];
}

// ---------------- z per-channel stats (channel-last) -----------------------
__global__ void zstat_part_kernel(const float* __restrict__ z) {
    int b = blockIdx.x, t = threadIdx.x;  // 96 blocks, 256 threads
    int c = t & 127, half = t >> 7;
    int start = b * 1536, end = start + 1536;
    float s = 0.f, s2 = 0.f;
    for (int p = start + half; p < end; p += 2) {
        float v = z[(size_t)p * 128 + c];
        s += v; s2 += v * v;
    }
    __shared__ float sh0[256], sh1[256];
    sh0[t] = s; sh1[t] = s2; __syncthreads();
    if (half == 0) {
        g_scratch[OFF_PART + (b * 128 + c) * 2 + 0] = sh0[t] + sh0[t + 128];
        g_scratch[OFF_PART + (b * 128 + c) * 2 + 1] = sh1[t] + sh1[t + 128];
    }
}

__global__ void zstat_fin_kernel() {
    int c = threadIdx.x;  // 128 threads
    float s = 0.f, s2 = 0.f;
    for (int b = 0; b < 96; b++) {
        s += g_scratch[OFF_PART + (b * 128 + c) * 2 + 0];
        s2 += g_scratch[OFF_PART + (b * 128 + c) * 2 + 1];
    }
    float m = s / (float)LL_;
    float var = s2 / (float)LL_ - m * m;
    float sc = rsqrtf(var + 1e-5f);
    ((float2*)(g_scratch + OFF_STZ))[c] = make_float2(sc, -m * sc);
}

// ---------------- weight transpose for conv_p: [co][c][tap] -> [c][tap][co] -
__global__ void wtrans_kernel(const float* __restrict__ w) {
    int e = blockIdx.x * 256 + threadIdx.x;
    if (e < 136 * 9 * 128) {
        int co = e & 127;
        int tap = (e >> 7) % 9;
        int c = e / (9 * 128);
        g_scratch[OFF_WT + e] = w[co * 1224 + c * 9 + tap];
    }
}

// ---------------- K10: conv_p 136 -> 128, norm folded, leaky, NHWC out -----
__global__ void __launch_bounds__(256) conv_p_kernel(const float* __restrict__ z,
                                                     const float* __restrict__ bias,
                                                     float* __restrict__ out) {
    __shared__ float s_in[3 * 34 * 8];     // [r][col][cl]
    __shared__ float s_w[8 * 9 * 128];     // [cl][tap][co]
    __shared__ float2 s_st[136];
    int i = blockIdx.y, j0 = blockIdx.x * 32, t = threadIdx.x;  // 256 threads
    const float* a2 = g_scratch + OFF_A2;
    const float* wT = g_scratch + OFF_WT;
    const float2* stats = (const float2*)(g_scratch + OFF_STZ);
    for (int e = t; e < 136; e += 256) s_st[e] = stats[e];

    int tp = t >> 5;   // 0..7 : pixels tp*4 .. tp*4+3
    int tc = t & 31;   // couts tc + 32k
    float acc[4][4] = {};

    for (int cb = 0; cb < 136; cb += 8) {
        __syncthreads();
        for (int e = t; e < 9216; e += 256) s_w[e] = wT[cb * 1152 + e];
        for (int e = t; e < 816; e += 256) {
            int cl = e & 7;
            int col = (e >> 3) % 34;
            int r = e / 272;
            int c = cb + cl;
            int gi = i - 1 + r, gj = j0 - 1 + col;
            float v = 0.f;
            if (gi >= 0 && gi < LDIM && gj >= 0 && gj < LDIM) {
                float raw = (c < 128) ? z[((size_t)gi * LDIM + gj) * 128 + c]
                                      : a2[(size_t)(c - 128) * LL_ + gi * LDIM + gj];
                float2 st = s_st[c];
                v = raw * st.x + st.y;
            }
            s_in[(r * 34 + col) * 8 + cl] = v;
        }
        __syncthreads();
        for (int cl = 0; cl < 8; cl++) {
            #pragma unroll
            for (int r = 0; r < 3; r++) {
                float iv[6];
                #pragma unroll
                for (int u = 0; u < 6; u++)
                    iv[u] = s_in[(r * 34 + tp * 4 + u) * 8 + cl];
                #pragma unroll
                for (int dc = 0; dc < 3; dc++) {
                    float wv[4];
                    #pragma unroll
                    for (int kk = 0; kk < 4; kk++)
                        wv[kk] = s_w[(cl * 9 + r * 3 + dc) * 128 + tc + 32 * kk];
                    #pragma unroll
                    for (int px = 0; px < 4; px++)
                        #pragma unroll
                        for (int kk = 0; kk < 4; kk++)
                            acc[px][kk] += iv[px + dc] * wv[kk];
                }
            }
        }
    }
    #pragma unroll
    for (int px = 0; px < 4; px++) {
        int j = j0 + tp * 4 + px;
        #pragma unroll
        for (int kk = 0; kk < 4; kk++) {
            int co = tc + 32 * kk;
            float v = acc[px][kk] + bias[co];
            out[((size_t)i * LDIM + j) * 128 + co] = v >= 0.f ? v : 0.01f * v;
        }
    }
}

// ---------------- host launcher --------------------------------------------
extern "C" void kernel_launch(void* const* d_in, const int* in_sizes, int n_in,
                              void* d_out, int out_size) {
    const float* x       = (const float*)d_in[0];
    const float* z       = (const float*)d_in[1];
    const float* plddt   = (const float*)d_in[2];
    const float* Wq      = (const float*)d_in[3];
    const float* Wk      = (const float*)d_in[4];
    const float* Wv      = (const float*)d_in[5];
    const float* Wp2a    = (const float*)d_in[6];
    const float* conv_a_w = (const float*)d_in[7];
    const float* conv_a_b = (const float*)d_in[8];
    const float* conv_m_w = (const float*)d_in[9];
    const float* conv_m_b = (const float*)d_in[10];
    const float* ln1_w   = (const float*)d_in[11];
    const float* ln1_b   = (const float*)d_in[12];
    const float* lin1_w  = (const float*)d_in[13];
    const float* lin1_b  = (const float*)d_in[14];
    const float* ln2_w   = (const float*)d_in[15];
    const float* ln2_b   = (const float*)d_in[16];
    const float* lin2_w  = (const float*)d_in[17];
    const float* lin2_b  = (const float*)d_in[18];
    const float* lnf_w   = (const float*)d_in[19];
    const float* lnf_b   = (const float*)d_in[20];
    const float* conv_p_w = (const float*)d_in[21];
    const float* conv_p_b = (const float*)d_in[22];

    float* xnew = (float*)d_out;                 // 384*256
    float* znew = (float*)d_out + 98304;         // 384*384*128

    float* sc = nullptr;
    cudaGetSymbolAddress((void**)&sc, g_scratch);
    float2* st0 = (float2*)(sc + OFF_ST0);
    float2* st1 = (float2*)(sc + OFF_ST1);
    float2* stz = (float2*)(sc + OFF_STZ);

    // node attention scores
    qkv_kernel<<<384, 256>>>(x, Wq, Wk, Wv);
    score_kernel<<<dim3(24, 384), 128>>>(z, Wp2a);

    // conv_a: instance-norm(16ch) + 3x3 + leaky
    stats_cf_kernel<<<16, 256>>>(sc + OFF_A0, st0);
    conv_cf_kernel<<<dim3(6, 384), 256>>>(sc + OFF_A0, 16, nullptr, 0,
                                          conv_a_w, conv_a_b, st0, sc + OFF_A1);
    // conv_m: instance-norm(8ch a1 + 1ch plddt) + 3x3 + leaky
    stats_cf_kernel<<<8, 256>>>(sc + OFF_A1, st1);
    stats_cf_kernel<<<1, 256>>>(plddt, st1 + 8);
    conv_cf_kernel<<<dim3(6, 384), 256>>>(sc + OFF_A1, 8, plddt, 1,
                                          conv_m_w, conv_m_b, st1, sc + OFF_A2);

    // aggregations + MLP + final LN -> x_new
    nfp_kernel<<<384, 128>>>(z);
    nfn_kernel<<<384, 256>>>();
    mlp1_kernel<<<384, 256>>>(ln1_w, ln1_b, lin1_w, lin1_b);
    mlp2_kernel<<<384, 256>>>(ln2_w, ln2_b, lin2_w, lin2_b, x, lnf_w, lnf_b, xnew);

    // pair update: instance-norm(z ++ a2) + conv 136->128 + leaky -> z_new
    zstat_part_kernel<<<96, 256>>>(z);
    zstat_fin_kernel<<<1, 128>>>();
    stats_cf_kernel<<<8, 256>>>(sc + OFF_A2, stz + 128);
    wtrans_kernel<<<612, 256>>>(conv_p_w);
    conv_p_kernel<<<dim3(12, 384), 256>>>(z, conv_p_b, znew);
}